// round 12
// baseline (speedup 1.0000x reference)
#include <cuda_runtime.h>
#include <cuda_fp16.h>
#include <math.h>
#include <stdint.h>

// Problem constants (DeBERTa layer)
#define BATCH 16
#define SEQ   512
#define HID   1024
#define NHEAD 8
#define HDIM  128
#define FFDIM 3072
#define MTOT  (BATCH * SEQ)        // 8192 rows
#define NBH   (BATCH * NHEAD)      // 128 (b,h) planes
#define QKVN  (3 * HID)            // 3072

// ---------------- scratch (device globals; no allocation allowed) ----------
__device__ __align__(16) float  g_h[(size_t)MTOT * HID];        // fp32 embed LN output (residual for proj_o)
__device__ __align__(16) __half g_h16[(size_t)MTOT * HID];      // embed fp16; later pre-LN2 (ff2 out)
__device__ __align__(16) __half g_qkv16[(size_t)MTOT * QKVN];   // [M][3072] = q|k|v
__device__ __align__(16) __half g_ctx16[(size_t)MTOT * HID];
__device__ __align__(16) __half g_attn16[(size_t)MTOT * HID];   // pre-LN1 then (in-place) attn_out
__device__ __align__(16) __half g_ff16[(size_t)MTOT * FFDIM];
__device__ __align__(16) float  g_bqkv[QKVN];                   // packed qkv bias
// fp16 transposed weights: [N, K] K-major
__device__ __align__(16) __half g_Wqkvt[(size_t)QKVN * HID];    // q|k|v rows
__device__ __align__(16) __half g_Wot[(size_t)HID * HID];
__device__ __align__(16) __half g_Wit[(size_t)FFDIM * HID];
__device__ __align__(16) __half g_Wft[(size_t)HID * FFDIM];

// ---------------- low-level helpers (base sm_103 features only) -----------
__device__ __forceinline__ uint32_t smem_u32(const void* p) {
    uint32_t a;
    asm("{ .reg .u64 t; cvta.to.shared.u64 t, %1; cvt.u32.u64 %0, t; }" : "=r"(a) : "l"(p));
    return a;
}
__device__ __forceinline__ void cpasync16(uint32_t dst, const void* src) {
    asm volatile("cp.async.cg.shared.global [%0], [%1], 16;" :: "r"(dst), "l"(src));
}
__device__ __forceinline__ void cp_commit() {
    asm volatile("cp.async.commit_group;" ::: "memory");
}
__device__ __forceinline__ void cp_wait0() { asm volatile("cp.async.wait_group 0;" ::: "memory"); }
__device__ __forceinline__ void cp_wait1() { asm volatile("cp.async.wait_group 1;" ::: "memory"); }
__device__ __forceinline__ void cp_wait2() { asm volatile("cp.async.wait_group 2;" ::: "memory"); }
__device__ __forceinline__ void cp_wait4() { asm volatile("cp.async.wait_group 4;" ::: "memory"); }
__device__ __forceinline__ void ldsm4(uint32_t* a, uint32_t addr) {
    asm volatile("ldmatrix.sync.aligned.m8n8.x4.shared.b16 {%0,%1,%2,%3}, [%4];"
                 : "=r"(a[0]), "=r"(a[1]), "=r"(a[2]), "=r"(a[3]) : "r"(addr));
}
__device__ __forceinline__ void ldsm4t(uint32_t* a, uint32_t addr) {
    asm volatile("ldmatrix.sync.aligned.m8n8.x4.trans.shared.b16 {%0,%1,%2,%3}, [%4];"
                 : "=r"(a[0]), "=r"(a[1]), "=r"(a[2]), "=r"(a[3]) : "r"(addr));
}
__device__ __forceinline__ void mma16816(float* c, const uint32_t* a, uint32_t b0, uint32_t b1) {
    asm volatile(
        "mma.sync.aligned.m16n8k16.row.col.f32.f16.f16.f32 "
        "{%0,%1,%2,%3}, {%4,%5,%6,%7}, {%8,%9}, {%0,%1,%2,%3};"
        : "+f"(c[0]), "+f"(c[1]), "+f"(c[2]), "+f"(c[3])
        : "r"(a[0]), "r"(a[1]), "r"(a[2]), "r"(a[3]), "r"(b0), "r"(b1));
}
__device__ __forceinline__ uint32_t packh2(float x, float y) {
    __half2 h = __floats2half2_rn(x, y);
    return *(uint32_t*)&h;
}

// ---------------- mma.sync GEMM: 128x128 tile, BK=32, 256 threads ----------
// 3-stage cp.async ring, one __syncthreads per K-chunk.
// C[m][n] = sum_k A[m][k] * B[n][k]; A,B fp16 K-major; pointers pre-offset to tile.
#define LDH 40                       // smem row stride in halves (80B): ldmatrix conflict-free
#define GST (128 * LDH * 2)          // 10240 B per matrix per stage
#define GSM3 (6 * GST)               // 3 stages x (A,B) = 61440 B

template <int HASBIAS, int HASRES, int GELU, int OUT16, int RES16>
__device__ __forceinline__ void tc_gemm(
    const __half* __restrict__ A, int lda,
    const __half* __restrict__ B, int ldb,
    void* __restrict__ Cv, int ldc, int K,
    const float* __restrict__ bias, const void* __restrict__ res) {
    extern __shared__ __align__(16) char smem[];
    const uint32_t sA0 = smem_u32(smem);             // 3 stages of A
    const uint32_t sB0 = sA0 + 3 * GST;              // 3 stages of B

    const int tid = threadIdx.x;
    const int lane = tid & 31;
    const int w = tid >> 5;
    const int wm = (w >> 2) * 64;   // warp M origin (2 rows of warps)
    const int wn = (w & 3) * 32;    // warp N origin (4 cols of warps)

    float acc[4][4][4];
#pragma unroll
    for (int i = 0; i < 4; i++)
#pragma unroll
        for (int j = 0; j < 4; j++)
#pragma unroll
            for (int e = 0; e < 4; e++) acc[i][j][e] = 0.0f;

    // global->smem mapping: thread covers row tid>>1, halves [(tid&1)*16, +16)
    const int lrow = tid >> 1;
    const int lcol = (tid & 1) * 16;
    const uint32_t dOff = (uint32_t)(lrow * LDH + lcol) * 2;

    const int nch = K >> 5;
    // ldmatrix lane addressing (n16k16 blocks; same for A and B)
    const int r8 = lane & 7;
    const int q4 = lane >> 3;
    const int fRow = (q4 & 1) * 8 + r8;
    const int fCol = (q4 >> 1) * 8;

#define LOAD_STAGE(s, k0)                                                          \
    {                                                                              \
        const __half* Ar = A + (size_t)lrow * lda + (k0) + lcol;                   \
        uint32_t da = sA0 + (s) * GST + dOff;                                      \
        cpasync16(da, Ar); cpasync16(da + 16, Ar + 8);                             \
        const __half* Br = B + (size_t)lrow * ldb + (k0) + lcol;                   \
        uint32_t db = sB0 + (s) * GST + dOff;                                      \
        cpasync16(db, Br); cpasync16(db + 16, Br + 8);                             \
        cp_commit();                                                               \
    }

    LOAD_STAGE(0, 0);
    LOAD_STAGE(1, 32);
    int s = 0, fill = 2;
    for (int c = 0; c < nch; c++) {
        if (c + 1 < nch) cp_wait1(); else cp_wait0();
        __syncthreads();
        if (c + 2 < nch) LOAD_STAGE(fill, (c + 2) * 32);

        const uint32_t baseA = sA0 + s * GST;
        const uint32_t baseB = sB0 + s * GST;
#pragma unroll
        for (int kk = 0; kk < 32; kk += 16) {
            uint32_t a[4][4], bb[2][4];
#pragma unroll
            for (int i = 0; i < 4; i++)
                ldsm4(a[i], baseA + (uint32_t)((wm + i * 16 + fRow) * LDH + kk + fCol) * 2);
#pragma unroll
            for (int j2 = 0; j2 < 2; j2++)
                ldsm4(bb[j2], baseB + (uint32_t)((wn + j2 * 16 + fRow) * LDH + kk + fCol) * 2);
#pragma unroll
            for (int i = 0; i < 4; i++)
#pragma unroll
                for (int j2 = 0; j2 < 2; j2++) {
                    mma16816(acc[i][2 * j2],     a[i], bb[j2][0], bb[j2][2]);
                    mma16816(acc[i][2 * j2 + 1], a[i], bb[j2][1], bb[j2][3]);
                }
        }
        s = (s == 2) ? 0 : s + 1;
        fill = (fill == 2) ? 0 : fill + 1;
    }
#undef LOAD_STAGE

    // epilogue
    const int gr = lane >> 2;         // 0..7
    const int gc = (lane & 3) * 2;    // 0,2,4,6
    float* Cf = (float*)Cv;
    __half* Ch = (__half*)Cv;
#pragma unroll
    for (int i = 0; i < 4; i++) {
#pragma unroll
        for (int j = 0; j < 4; j++) {
            const int col = wn + j * 8 + gc;
            float bx = 0.f, by = 0.f;
            if (HASBIAS) { bx = bias[col]; by = bias[col + 1]; }
#pragma unroll
            for (int hf = 0; hf < 2; hf++) {
                const int row = wm + i * 16 + gr + hf * 8;
                float v0 = acc[i][j][hf * 2 + 0];
                float v1 = acc[i][j][hf * 2 + 1];
                if (HASBIAS) { v0 += bx; v1 += by; }
                if (HASRES) {
                    if (RES16) {
                        const __half* rp = (const __half*)res + (size_t)row * ldc + col;
                        __half2 rh = *(const __half2*)rp;
                        v0 += __low2float(rh); v1 += __high2float(rh);
                    } else {
                        const float* rp = (const float*)res + (size_t)row * ldc + col;
                        v0 += rp[0]; v1 += rp[1];
                    }
                }
                if (GELU) {
                    v0 = 0.5f * v0 * (1.0f + erff(v0 * 0.70710678118654752f));
                    v1 = 0.5f * v1 * (1.0f + erff(v1 * 0.70710678118654752f));
                }
                if (OUT16) {
                    __half2 h = __floats2half2_rn(v0, v1);
                    *(__half2*)(Ch + (size_t)row * ldc + col) = h;
                } else {
                    *(float2*)(Cf + (size_t)row * ldc + col) = make_float2(v0, v1);
                }
            }
        }
    }
}

// ---------------- GEMM wrapper kernels ----------------
__global__ void __launch_bounds__(256, 2) k_qkv() {
    int tM = blockIdx.y * 128, tN = blockIdx.x * 128;
    tc_gemm<1, 0, 0, 1, 0>(g_h16 + (size_t)tM * HID, HID, g_Wqkvt + (size_t)tN * HID, HID,
                           g_qkv16 + (size_t)tM * QKVN + tN, QKVN, HID, g_bqkv + tN, nullptr);
}
// pre-LN1 = ctx @ Wo + bo + h  -> fp16 g_attn16
__global__ void __launch_bounds__(256, 2) k_proj_o(const float* __restrict__ bias) {
    int tM = blockIdx.y * 128, tN = blockIdx.x * 128;
    tc_gemm<1, 1, 0, 1, 0>(g_ctx16 + (size_t)tM * HID, HID, g_Wot + (size_t)tN * HID, HID,
                           g_attn16 + (size_t)tM * HID + tN, HID, HID, bias + tN,
                           g_h + (size_t)tM * HID + tN);
}
__global__ void __launch_bounds__(256, 2) k_ff1(const float* __restrict__ bias) {
    int tM = blockIdx.y * 128, tN = blockIdx.x * 128;
    tc_gemm<1, 0, 1, 1, 0>(g_attn16 + (size_t)tM * HID, HID, g_Wit + (size_t)tN * HID, HID,
                           g_ff16 + (size_t)tM * FFDIM + tN, FFDIM, HID, bias + tN, nullptr);
}
// pre-LN2 = ff @ Wf + bf + attn_out(fp16) -> fp16 g_h16 (dead after qkv)
__global__ void __launch_bounds__(256, 2) k_ff2(const float* __restrict__ bias) {
    int tM = blockIdx.y * 128, tN = blockIdx.x * 128;
    tc_gemm<1, 1, 0, 1, 1>(g_ff16 + (size_t)tM * FFDIM, FFDIM, g_Wft + (size_t)tN * FFDIM, FFDIM,
                           g_h16 + (size_t)tM * HID + tN, HID, FFDIM, bias + tN,
                           g_attn16 + (size_t)tM * HID + tN);
}

// ---------------- fused flash attention (128 q-rows, 256 thr, double-buffered) ----
#define FLD 136                          // smem halves stride (272B: conflict-free)
#define FTILE (128 * FLD * 2)            // 34816 B
#define FSM_TOTAL (5 * FTILE)            // Q + 2K + 2V = 174080 B

__global__ void __launch_bounds__(256) k_flash() {
    extern __shared__ __align__(16) char smem[];
    const uint32_t sQ = smem_u32(smem);
    const uint32_t sK = sQ + FTILE;       // 2 stages
    const uint32_t sV = sQ + 3 * FTILE;   // 2 stages

    const int tid = threadIdx.x;
    const int lane = tid & 31;
    const int w = tid >> 5;
    const int bh = blockIdx.y;
    const int b = bh >> 3, h = bh & 7;
    const int tQ = blockIdx.x * 128;

    const int r8 = lane & 7;
    const int q4 = lane >> 3;
    const int fRow = (q4 & 1) * 8 + r8;
    const int fCol = (q4 >> 1) * 8;

    const int lrow = tid >> 1;
    const int lcol = (tid & 1) * 64;
    const uint32_t dOff = (uint32_t)(lrow * FLD + lcol) * 2;

    const __half* Qg = g_qkv16 + ((size_t)(b * SEQ + tQ + lrow) * QKVN + h * HDIM + lcol);
    const __half* Kg0 = g_qkv16 + ((size_t)(b * SEQ + lrow) * QKVN + HID + h * HDIM + lcol);
    const __half* Vg0 = g_qkv16 + ((size_t)(b * SEQ + lrow) * QKVN + 2 * HID + h * HDIM + lcol);

#define CP_TILE(dstbase, src)                                   \
    {                                                           \
        uint32_t d = (dstbase) + dOff;                          \
        const __half* sp = (src);                               \
        _Pragma("unroll")                                       \
        for (int i = 0; i < 8; i++) cpasync16(d + i * 16, sp + i * 8); \
        cp_commit();                                            \
    }

    CP_TILE(sQ, Qg);
    CP_TILE(sK, Kg0);
    CP_TILE(sV, Vg0);
    CP_TILE(sK + FTILE, Kg0 + (size_t)128 * QKVN);
    CP_TILE(sV + FTILE, Vg0 + (size_t)128 * QKVN);

    cp_wait4();
    __syncthreads();

    uint32_t qf[8][4];
#pragma unroll
    for (int kk = 0; kk < 8; kk++)
        ldsm4(qf[kk], sQ + (uint32_t)((16 * w + fRow) * FLD + kk * 16 + fCol) * 2);

    float o[16][4];
#pragma unroll
    for (int nt = 0; nt < 16; nt++)
#pragma unroll
        for (int e = 0; e < 4; e++) o[nt][e] = 0.0f;
    float m0 = -INFINITY, m1 = -INFINITY, l0 = 0.0f, l1 = 0.0f;
    const float scale = 0.08838834764831843f;

    for (int j = 0; j < 4; j++) {
        if (j < 3) cp_wait2(); else cp_wait0();
        __syncthreads();
        const uint32_t Kb = sK + (j & 1) * FTILE;
        const uint32_t Vb = sV + (j & 1) * FTILE;

        float s[16][4];
#pragma unroll
        for (int nt = 0; nt < 16; nt++)
#pragma unroll
            for (int e = 0; e < 4; e++) s[nt][e] = 0.0f;
#pragma unroll
        for (int kk = 0; kk < 8; kk++) {
#pragma unroll
            for (int nt2 = 0; nt2 < 8; nt2++) {
                uint32_t t[4];
                ldsm4(t, Kb + (uint32_t)((nt2 * 16 + fRow) * FLD + kk * 16 + fCol) * 2);
                mma16816(s[2 * nt2],     qf[kk], t[0], t[2]);
                mma16816(s[2 * nt2 + 1], qf[kk], t[1], t[3]);
            }
        }
        __syncthreads();
        if (j < 2) CP_TILE(sK + (j & 1) * FTILE, Kg0 + (size_t)(j + 2) * 128 * QKVN);

        float mx0 = -INFINITY, mx1 = -INFINITY;
#pragma unroll
        for (int nt = 0; nt < 16; nt++) {
#pragma unroll
            for (int e = 0; e < 4; e++) s[nt][e] *= scale;
            mx0 = fmaxf(mx0, fmaxf(s[nt][0], s[nt][1]));
            mx1 = fmaxf(mx1, fmaxf(s[nt][2], s[nt][3]));
        }
        mx0 = fmaxf(mx0, __shfl_xor_sync(0xffffffffu, mx0, 1));
        mx0 = fmaxf(mx0, __shfl_xor_sync(0xffffffffu, mx0, 2));
        mx1 = fmaxf(mx1, __shfl_xor_sync(0xffffffffu, mx1, 1));
        mx1 = fmaxf(mx1, __shfl_xor_sync(0xffffffffu, mx1, 2));
        const float mn0 = fmaxf(m0, mx0), mn1 = fmaxf(m1, mx1);
        const float c0 = __expf(m0 - mn0), c1 = __expf(m1 - mn1);
        m0 = mn0; m1 = mn1;
        float rs0 = 0.0f, rs1 = 0.0f;
#pragma unroll
        for (int nt = 0; nt < 16; nt++) {
            s[nt][0] = __expf(s[nt][0] - mn0); s[nt][1] = __expf(s[nt][1] - mn0);
            s[nt][2] = __expf(s[nt][2] - mn1); s[nt][3] = __expf(s[nt][3] - mn1);
            rs0 += s[nt][0] + s[nt][1];
            rs1 += s[nt][2] + s[nt][3];
            o[nt][0] *= c0; o[nt][1] *= c0; o[nt][2] *= c1; o[nt][3] *= c1;
        }
        rs0 += __shfl_xor_sync(0xffffffffu, rs0, 1);
        rs0 += __shfl_xor_sync(0xffffffffu, rs0, 2);
        rs1 += __shfl_xor_sync(0xffffffffu, rs1, 1);
        rs1 += __shfl_xor_sync(0xffffffffu, rs1, 2);
        l0 = l0 * c0 + rs0;
        l1 = l1 * c1 + rs1;

#pragma unroll
        for (int kk = 0; kk < 8; kk++) {
            uint32_t a[4];
            a[0] = packh2(s[2 * kk][0], s[2 * kk][1]);
            a[1] = packh2(s[2 * kk][2], s[2 * kk][3]);
            a[2] = packh2(s[2 * kk + 1][0], s[2 * kk + 1][1]);
            a[3] = packh2(s[2 * kk + 1][2], s[2 * kk + 1][3]);
#pragma unroll
            for (int nt2 = 0; nt2 < 8; nt2++) {
                uint32_t t[4];
                ldsm4t(t, Vb + (uint32_t)((kk * 16 + fRow) * FLD + nt2 * 16 + fCol) * 2);
                mma16816(o[2 * nt2],     a, t[0], t[1]);
                mma16816(o[2 * nt2 + 1], a, t[2], t[3]);
            }
        }
        __syncthreads();
        if (j < 2) CP_TILE(sV + (j & 1) * FTILE, Vg0 + (size_t)(j + 2) * 128 * QKVN);
    }
#undef CP_TILE

    const int gr = lane >> 2;
    const int gc = (lane & 3) * 2;
    const float li0 = 1.0f / l0, li1 = 1.0f / l1;
    const size_t row0 = (size_t)(b * SEQ + tQ + 16 * w + gr) * HID + h * HDIM;
    const size_t row1 = row0 + (size_t)8 * HID;
#pragma unroll
    for (int nt = 0; nt < 16; nt++) {
        const int col = nt * 8 + gc;
        __half2 h0 = __floats2half2_rn(o[nt][0] * li0, o[nt][1] * li0);
        __half2 h1 = __floats2half2_rn(o[nt][2] * li1, o[nt][3] * li1);
        *(__half2*)(g_ctx16 + row0 + col) = h0;
        *(__half2*)(g_ctx16 + row1 + col) = h1;
    }
}

// ---------------- weight transpose + fp32->fp16 convert: W[K,N] -> Wt[N,K] ----
__global__ void __launch_bounds__(256) k_wt(const float* __restrict__ W, __half* __restrict__ Wt,
                                            int K, int N) {
    __shared__ float t[32][33];
    int nb = blockIdx.x * 32, kb = blockIdx.y * 32;
    int tx = threadIdx.x & 31, ty = threadIdx.x >> 5;
#pragma unroll
    for (int j = 0; j < 4; j++)
        t[ty + 8 * j][tx] = W[(size_t)(kb + ty + 8 * j) * N + nb + tx];
    __syncthreads();
#pragma unroll
    for (int j = 0; j < 4; j++)
        Wt[(size_t)(nb + ty + 8 * j) * K + kb + tx] = __float2half(t[tx][ty + 8 * j]);
}

// QKV weights: z selects Wq/Wk/Wv, writes into g_Wqkvt rows z*1024 + n
__global__ void __launch_bounds__(256) k_wt_qkv(const float* __restrict__ Wq,
                                                const float* __restrict__ Wk,
                                                const float* __restrict__ Wv) {
    __shared__ float t[32][33];
    const float* W = (blockIdx.z == 0) ? Wq : (blockIdx.z == 1) ? Wk : Wv;
    int nb = blockIdx.x * 32, kb = blockIdx.y * 32;
    int tx = threadIdx.x & 31, ty = threadIdx.x >> 5;
#pragma unroll
    for (int j = 0; j < 4; j++)
        t[ty + 8 * j][tx] = W[(size_t)(kb + ty + 8 * j) * HID + nb + tx];
    __syncthreads();
    __half* Wt = g_Wqkvt + (size_t)blockIdx.z * HID * HID;
#pragma unroll
    for (int j = 0; j < 4; j++)
        Wt[(size_t)(nb + ty + 8 * j) * HID + kb + tx] = __float2half(t[tx][ty + 8 * j]);
}

// packed qkv bias
__global__ void __launch_bounds__(256) k_bias_pack(const float* __restrict__ qb,
                                                   const float* __restrict__ vb) {
    int i = blockIdx.x * 256 + threadIdx.x;
    float v = 0.0f;
    if (i < HID) v = qb[i];
    else if (i >= 2 * HID) v = vb[i - 2 * HID];
    g_bqkv[i] = v;
}

// ---------------- reductions / LN ----------------
__device__ __forceinline__ float warpSum(float v) {
#pragma unroll
    for (int o = 16; o > 0; o >>= 1) v += __shfl_xor_sync(0xffffffffu, v, o);
    return v;
}

__device__ __forceinline__ void ln_store(float4 v, const float* __restrict__ g,
                                         const float* __restrict__ b,
                                         float* __restrict__ outrow,
                                         __half* __restrict__ outrow16, int t) {
    __shared__ float red[8];
    __shared__ float stat[2];
    float s = v.x + v.y + v.z + v.w;
    s = warpSum(s);
    if ((t & 31) == 0) red[t >> 5] = s;
    __syncthreads();
    if (t < 32) {
        float x = (t < 8) ? red[t] : 0.0f;
        x = warpSum(x);
        if (t == 0) stat[0] = x * (1.0f / (float)HID);
    }
    __syncthreads();
    float m = stat[0];
    float dx = v.x - m, dy = v.y - m, dz = v.z - m, dw = v.w - m;
    float s2 = dx * dx + dy * dy + dz * dz + dw * dw;
    s2 = warpSum(s2);
    if ((t & 31) == 0) red[t >> 5] = s2;
    __syncthreads();
    if (t < 32) {
        float x = (t < 8) ? red[t] : 0.0f;
        x = warpSum(x);
        if (t == 0) stat[1] = rsqrtf(x * (1.0f / (float)HID) + 1e-7f);
    }
    __syncthreads();
    float r = stat[1];
    float4 gv = ((const float4*)g)[t];
    float4 bv = ((const float4*)b)[t];
    float4 o;
    o.x = dx * r * gv.x + bv.x;
    o.y = dy * r * gv.y + bv.y;
    o.z = dz * r * gv.z + bv.z;
    o.w = dw * r * gv.w + bv.w;
    if (outrow) ((float4*)outrow)[t] = o;
    if (outrow16) {
        __half2 h0 = __floats2half2_rn(o.x, o.y);
        __half2 h1 = __floats2half2_rn(o.z, o.w);
        uint2 u;
        u.x = *(uint32_t*)&h0; u.y = *(uint32_t*)&h1;
        ((uint2*)outrow16)[t] = u;
    }
}

__global__ void __launch_bounds__(256) k_embed(const float* __restrict__ x,
                                               const float* __restrict__ pos,
                                               const float* __restrict__ g,
                                               const float* __restrict__ b) {
    int row = blockIdx.x;
    int s = row & (SEQ - 1);
    int t = threadIdx.x;
    float4 xv = ((const float4*)(x + (size_t)row * HID))[t];
    float4 pv = ((const float4*)(pos + (size_t)s * HID))[t];
    xv.x += pv.x; xv.y += pv.y; xv.z += pv.z; xv.w += pv.w;
    ln_store(xv, g, b, g_h + (size_t)row * HID, g_h16 + (size_t)row * HID, t);
}

// LN1: fp16 in (g_attn16 pre-LN), fp16 out IN PLACE (attn_out)
__global__ void __launch_bounds__(256) k_ln1(const float* __restrict__ g,
                                             const float* __restrict__ b) {
    int row = blockIdx.x;
    int t = threadIdx.x;
    __half* p = g_attn16 + (size_t)row * HID;
    uint2 u = ((const uint2*)p)[t];
    __half2 h0 = *(__half2*)&u.x, h1 = *(__half2*)&u.y;
    float4 v = make_float4(__low2float(h0), __high2float(h0),
                           __low2float(h1), __high2float(h1));
    ln_store(v, g, b, (float*)nullptr, p, t);
}

// LN2: fp16 in (g_h16 pre-LN2), fp32 out
__global__ void __launch_bounds__(256) k_ln2(const float* __restrict__ g,
                                             const float* __restrict__ b,
                                             float* __restrict__ out) {
    int row = blockIdx.x;
    int t = threadIdx.x;
    const __half* p = g_h16 + (size_t)row * HID;
    uint2 u = ((const uint2*)p)[t];
    __half2 h0 = *(__half2*)&u.x, h1 = *(__half2*)&u.y;
    float4 v = make_float4(__low2float(h0), __high2float(h0),
                           __low2float(h1), __high2float(h1));
    ln_store(v, g, b, out + (size_t)row * HID, (__half*)nullptr, t);
}

// ---------------- launch ----------------
extern "C" void kernel_launch(void* const* d_in, const int* in_sizes, int n_in,
                              void* d_out, int out_size) {
    const float* x        = (const float*)d_in[0];
    const float* pos_emb  = (const float*)d_in[1];
    const float* emb_ln_g = (const float*)d_in[2];
    const float* emb_ln_b = (const float*)d_in[3];
    const float* Wq       = (const float*)d_in[4];
    const float* Wk       = (const float*)d_in[5];
    const float* Wv       = (const float*)d_in[6];
    const float* q_bias   = (const float*)d_in[7];
    const float* v_bias   = (const float*)d_in[8];
    const float* Wo       = (const float*)d_in[9];
    const float* bo       = (const float*)d_in[10];
    const float* ln1_g    = (const float*)d_in[11];
    const float* ln1_b    = (const float*)d_in[12];
    const float* Wi       = (const float*)d_in[13];
    const float* bi       = (const float*)d_in[14];
    const float* Wf       = (const float*)d_in[15];
    const float* bf       = (const float*)d_in[16];
    const float* ln2_g    = (const float*)d_in[17];
    const float* ln2_b    = (const float*)d_in[18];
    float* out = (float*)d_out;

    __half *wot, *wit, *wft;
    cudaGetSymbolAddress((void**)&wot, g_Wot);
    cudaGetSymbolAddress((void**)&wit, g_Wit);
    cudaGetSymbolAddress((void**)&wft, g_Wft);

    static cudaStream_t s2 = nullptr;
    static cudaEvent_t evFork = nullptr, evJoin1 = nullptr, evJoin2 = nullptr;
    if (!s2) {
        cudaStreamCreateWithFlags(&s2, cudaStreamNonBlocking);
        cudaEventCreateWithFlags(&evFork, cudaEventDisableTiming);
        cudaEventCreateWithFlags(&evJoin1, cudaEventDisableTiming);
        cudaEventCreateWithFlags(&evJoin2, cudaEventDisableTiming);
    }

    cudaFuncSetAttribute(k_qkv, cudaFuncAttributeMaxDynamicSharedMemorySize, GSM3);
    cudaFuncSetAttribute(k_proj_o, cudaFuncAttributeMaxDynamicSharedMemorySize, GSM3);
    cudaFuncSetAttribute(k_ff1, cudaFuncAttributeMaxDynamicSharedMemorySize, GSM3);
    cudaFuncSetAttribute(k_ff2, cudaFuncAttributeMaxDynamicSharedMemorySize, GSM3);
    cudaFuncSetAttribute(k_flash, cudaFuncAttributeMaxDynamicSharedMemorySize, FSM_TOTAL);

    // fork: weight prep on s2 runs concurrently with embed/qkv/flash on main
    cudaEventRecord(evFork, 0);
    cudaStreamWaitEvent(s2, evFork, 0);
    k_bias_pack<<<QKVN / 256, 256, 0, s2>>>(q_bias, v_bias);
    k_wt_qkv<<<dim3(HID / 32, HID / 32, 3), 256, 0, s2>>>(Wq, Wk, Wv);
    cudaEventRecord(evJoin1, s2);   // qkv weights + bias ready
    k_wt<<<dim3(HID / 32, HID / 32), 256, 0, s2>>>(Wo, wot, HID, HID);
    k_wt<<<dim3(FFDIM / 32, HID / 32), 256, 0, s2>>>(Wi, wit, HID, FFDIM);
    k_wt<<<dim3(HID / 32, FFDIM / 32), 256, 0, s2>>>(Wf, wft, FFDIM, HID);
    cudaEventRecord(evJoin2, s2);   // Wo/Wi/Wf ready

    k_embed<<<MTOT, 256>>>(x, pos_emb, emb_ln_g, emb_ln_b);
    cudaStreamWaitEvent(0, evJoin1, 0);  // need qkv weights now

    dim3 gQKV(QKVN / 128, MTOT / 128);     // (24, 64)
    dim3 gProj(HID / 128, MTOT / 128);     // (8, 64)
    dim3 gFF1(FFDIM / 128, MTOT / 128);    // (24, 64)
    dim3 gFlash(SEQ / 128, NBH);           // (4, 128)

    k_qkv<<<gQKV, 256, GSM3>>>();
    k_flash<<<gFlash, 256, FSM_TOTAL>>>();
    cudaStreamWaitEvent(0, evJoin2, 0);  // need Wo (and later Wi/Wf)
    k_proj_o<<<gProj, 256, GSM3>>>(bo);
    k_ln1<<<MTOT, 256>>>(ln1_g, ln1_b);
    k_ff1<<<gFF1, 256, GSM3>>>(bi);
    k_ff2<<<gProj, 256, GSM3>>>(bf);
    k_ln2<<<MTOT, 256>>>(ln2_g, ln2_b, out);
}

// round 13
// speedup vs baseline: 1.0163x; 1.0163x over previous
#include <cuda_runtime.h>
#include <cuda_fp16.h>
#include <math.h>
#include <stdint.h>

// Problem constants (DeBERTa layer)
#define BATCH 16
#define SEQ   512
#define HID   1024
#define NHEAD 8
#define HDIM  128
#define FFDIM 3072
#define MTOT  (BATCH * SEQ)        // 8192 rows
#define NBH   (BATCH * NHEAD)      // 128 (b,h) planes
#define QKVN  (3 * HID)            // 3072

// ---------------- scratch (device globals; no allocation allowed) ----------
__device__ __align__(16) float  g_h[(size_t)MTOT * HID];        // fp32 residual stream
__device__ __align__(16) float  g_attn32[(size_t)MTOT * HID];   // fp32 attn_out (residual for FF2)
__device__ __align__(16) __half g_h16[(size_t)MTOT * HID];
__device__ __align__(16) __half g_qkv16[(size_t)MTOT * QKVN];   // [M][3072] = q|k|v
__device__ __align__(16) __half g_ctx16[(size_t)MTOT * HID];
__device__ __align__(16) __half g_attn16[(size_t)MTOT * HID];
__device__ __align__(16) __half g_ff16[(size_t)MTOT * FFDIM];
__device__ __align__(16) float  g_bqkv[QKVN];                   // packed qkv bias
// fp16 transposed weights: [N, K] K-major
__device__ __align__(16) __half g_Wqkvt[(size_t)QKVN * HID];    // q|k|v rows
__device__ __align__(16) __half g_Wot[(size_t)HID * HID];
__device__ __align__(16) __half g_Wit[(size_t)FFDIM * HID];
__device__ __align__(16) __half g_Wft[(size_t)HID * FFDIM];

// ---------------- low-level helpers (base sm_103 features only) -----------
__device__ __forceinline__ uint32_t smem_u32(const void* p) {
    uint32_t a;
    asm("{ .reg .u64 t; cvta.to.shared.u64 t, %1; cvt.u32.u64 %0, t; }" : "=r"(a) : "l"(p));
    return a;
}
__device__ __forceinline__ void cpasync16(uint32_t dst, const void* src) {
    asm volatile("cp.async.cg.shared.global [%0], [%1], 16;" :: "r"(dst), "l"(src));
}
__device__ __forceinline__ void cp_commit() {
    asm volatile("cp.async.commit_group;" ::: "memory");
}
__device__ __forceinline__ void cp_wait0() { asm volatile("cp.async.wait_group 0;" ::: "memory"); }
__device__ __forceinline__ void cp_wait1() { asm volatile("cp.async.wait_group 1;" ::: "memory"); }
__device__ __forceinline__ void cp_wait2() { asm volatile("cp.async.wait_group 2;" ::: "memory"); }
__device__ __forceinline__ void cp_wait4() { asm volatile("cp.async.wait_group 4;" ::: "memory"); }
__device__ __forceinline__ void ldsm4(uint32_t* a, uint32_t addr) {
    asm volatile("ldmatrix.sync.aligned.m8n8.x4.shared.b16 {%0,%1,%2,%3}, [%4];"
                 : "=r"(a[0]), "=r"(a[1]), "=r"(a[2]), "=r"(a[3]) : "r"(addr));
}
__device__ __forceinline__ void ldsm4t(uint32_t* a, uint32_t addr) {
    asm volatile("ldmatrix.sync.aligned.m8n8.x4.trans.shared.b16 {%0,%1,%2,%3}, [%4];"
                 : "=r"(a[0]), "=r"(a[1]), "=r"(a[2]), "=r"(a[3]) : "r"(addr));
}
__device__ __forceinline__ void mma16816(float* c, const uint32_t* a, uint32_t b0, uint32_t b1) {
    asm volatile(
        "mma.sync.aligned.m16n8k16.row.col.f32.f16.f16.f32 "
        "{%0,%1,%2,%3}, {%4,%5,%6,%7}, {%8,%9}, {%0,%1,%2,%3};"
        : "+f"(c[0]), "+f"(c[1]), "+f"(c[2]), "+f"(c[3])
        : "r"(a[0]), "r"(a[1]), "r"(a[2]), "r"(a[3]), "r"(b0), "r"(b1));
}
__device__ __forceinline__ uint32_t packh2(float x, float y) {
    __half2 h = __floats2half2_rn(x, y);
    return *(uint32_t*)&h;
}

// ---------------- mma.sync GEMM: 128x128 tile, BK=32, 256 threads ----------
// 3-stage cp.async ring, one __syncthreads per K-chunk.
// C[m][n] = sum_k A[m][k] * B[n][k]; A,B fp16 K-major; pointers pre-offset to tile.
#define LDH 40                       // smem row stride in halves (80B): ldmatrix conflict-free
#define GST (128 * LDH * 2)          // 10240 B per matrix per stage
#define GSM3 (6 * GST)               // 3 stages x (A,B) = 61440 B

template <int HASBIAS, int HASRES, int GELU, int OUT16>
__device__ __forceinline__ void tc_gemm(
    const __half* __restrict__ A, int lda,
    const __half* __restrict__ B, int ldb,
    void* __restrict__ Cv, int ldc, int K,
    const float* __restrict__ bias, const float* __restrict__ res) {
    extern __shared__ __align__(16) char smem[];
    const uint32_t sA0 = smem_u32(smem);             // 3 stages of A
    const uint32_t sB0 = sA0 + 3 * GST;              // 3 stages of B

    const int tid = threadIdx.x;
    const int lane = tid & 31;
    const int w = tid >> 5;
    const int wm = (w >> 2) * 64;   // warp M origin (2 rows of warps)
    const int wn = (w & 3) * 32;    // warp N origin (4 cols of warps)

    float acc[4][4][4];
#pragma unroll
    for (int i = 0; i < 4; i++)
#pragma unroll
        for (int j = 0; j < 4; j++)
#pragma unroll
            for (int e = 0; e < 4; e++) acc[i][j][e] = 0.0f;

    // global->smem mapping: thread covers row tid>>1, halves [(tid&1)*16, +16)
    const int lrow = tid >> 1;
    const int lcol = (tid & 1) * 16;
    const uint32_t dOff = (uint32_t)(lrow * LDH + lcol) * 2;

    const int nch = K >> 5;
    // ldmatrix lane addressing (n16k16 blocks; same for A and B)
    const int r8 = lane & 7;
    const int q4 = lane >> 3;
    const int fRow = (q4 & 1) * 8 + r8;
    const int fCol = (q4 >> 1) * 8;

#define LOAD_STAGE(s, k0)                                                          \
    {                                                                              \
        const __half* Ar = A + (size_t)lrow * lda + (k0) + lcol;                   \
        uint32_t da = sA0 + (s) * GST + dOff;                                      \
        cpasync16(da, Ar); cpasync16(da + 16, Ar + 8);                             \
        const __half* Br = B + (size_t)lrow * ldb + (k0) + lcol;                   \
        uint32_t db = sB0 + (s) * GST + dOff;                                      \
        cpasync16(db, Br); cpasync16(db + 16, Br + 8);                             \
        cp_commit();                                                               \
    }

    LOAD_STAGE(0, 0);
    LOAD_STAGE(1, 32);
    int s = 0, fill = 2;
    for (int c = 0; c < nch; c++) {
        if (c + 1 < nch) cp_wait1(); else cp_wait0();
        __syncthreads();
        if (c + 2 < nch) LOAD_STAGE(fill, (c + 2) * 32);

        const uint32_t baseA = sA0 + s * GST;
        const uint32_t baseB = sB0 + s * GST;
#pragma unroll
        for (int kk = 0; kk < 32; kk += 16) {
            uint32_t a[4][4], bb[2][4];
#pragma unroll
            for (int i = 0; i < 4; i++)
                ldsm4(a[i], baseA + (uint32_t)((wm + i * 16 + fRow) * LDH + kk + fCol) * 2);
#pragma unroll
            for (int j2 = 0; j2 < 2; j2++)
                ldsm4(bb[j2], baseB + (uint32_t)((wn + j2 * 16 + fRow) * LDH + kk + fCol) * 2);
#pragma unroll
            for (int i = 0; i < 4; i++)
#pragma unroll
                for (int j2 = 0; j2 < 2; j2++) {
                    mma16816(acc[i][2 * j2],     a[i], bb[j2][0], bb[j2][2]);
                    mma16816(acc[i][2 * j2 + 1], a[i], bb[j2][1], bb[j2][3]);
                }
        }
        s = (s == 2) ? 0 : s + 1;
        fill = (fill == 2) ? 0 : fill + 1;
    }
#undef LOAD_STAGE

    // epilogue
    const int gr = lane >> 2;         // 0..7
    const int gc = (lane & 3) * 2;    // 0,2,4,6
    float* Cf = (float*)Cv;
    __half* Ch = (__half*)Cv;
#pragma unroll
    for (int i = 0; i < 4; i++) {
#pragma unroll
        for (int j = 0; j < 4; j++) {
            const int col = wn + j * 8 + gc;
            float bx = 0.f, by = 0.f;
            if (HASBIAS) { bx = bias[col]; by = bias[col + 1]; }
#pragma unroll
            for (int hf = 0; hf < 2; hf++) {
                const int row = wm + i * 16 + gr + hf * 8;
                float v0 = acc[i][j][hf * 2 + 0];
                float v1 = acc[i][j][hf * 2 + 1];
                if (HASBIAS) { v0 += bx; v1 += by; }
                if (HASRES) {
                    const float* rp = res + (size_t)row * ldc + col;
                    v0 += rp[0]; v1 += rp[1];
                }
                if (GELU) {
                    v0 = 0.5f * v0 * (1.0f + erff(v0 * 0.70710678118654752f));
                    v1 = 0.5f * v1 * (1.0f + erff(v1 * 0.70710678118654752f));
                }
                if (OUT16) {
                    __half2 h = __floats2half2_rn(v0, v1);
                    *(__half2*)(Ch + (size_t)row * ldc + col) = h;
                } else {
                    *(float2*)(Cf + (size_t)row * ldc + col) = make_float2(v0, v1);
                }
            }
        }
    }
}

// ---------------- GEMM wrapper kernels ----------------
__global__ void __launch_bounds__(256, 2) k_qkv() {
    int tM = blockIdx.y * 128, tN = blockIdx.x * 128;
    tc_gemm<1, 0, 0, 1>(g_h16 + (size_t)tM * HID, HID, g_Wqkvt + (size_t)tN * HID, HID,
                        g_qkv16 + (size_t)tM * QKVN + tN, QKVN, HID, g_bqkv + tN, nullptr);
}
__global__ void __launch_bounds__(256, 2) k_proj_o(const float* __restrict__ bias) {
    int tM = blockIdx.y * 128, tN = blockIdx.x * 128;
    tc_gemm<1, 1, 0, 0>(g_ctx16 + (size_t)tM * HID, HID, g_Wot + (size_t)tN * HID, HID,
                        g_h + (size_t)tM * HID + tN, HID, HID, bias + tN,
                        g_h + (size_t)tM * HID + tN);
}
__global__ void __launch_bounds__(256, 2) k_ff1(const float* __restrict__ bias) {
    int tM = blockIdx.y * 128, tN = blockIdx.x * 128;
    tc_gemm<1, 0, 1, 1>(g_attn16 + (size_t)tM * HID, HID, g_Wit + (size_t)tN * HID, HID,
                        g_ff16 + (size_t)tM * FFDIM + tN, FFDIM, HID, bias + tN, nullptr);
}
__global__ void __launch_bounds__(256, 2) k_ff2(const float* __restrict__ bias) {
    int tM = blockIdx.y * 128, tN = blockIdx.x * 128;
    tc_gemm<1, 1, 0, 0>(g_ff16 + (size_t)tM * FFDIM, FFDIM, g_Wft + (size_t)tN * FFDIM, FFDIM,
                        g_h + (size_t)tM * HID + tN, HID, FFDIM, bias + tN,
                        g_attn32 + (size_t)tM * HID + tN);
}

// ---------------- fused flash attention (128 q-rows, 256 thr, double-buffered) ----
#define FLD 136                          // smem halves stride (272B: conflict-free)
#define FTILE (128 * FLD * 2)            // 34816 B
#define FSM_TOTAL (5 * FTILE)            // Q + 2K + 2V = 174080 B

__global__ void __launch_bounds__(256) k_flash() {
    extern __shared__ __align__(16) char smem[];
    const uint32_t sQ = smem_u32(smem);
    const uint32_t sK = sQ + FTILE;       // 2 stages
    const uint32_t sV = sQ + 3 * FTILE;   // 2 stages

    const int tid = threadIdx.x;
    const int lane = tid & 31;
    const int w = tid >> 5;
    const int bh = blockIdx.y;
    const int b = bh >> 3, h = bh & 7;
    const int tQ = blockIdx.x * 128;

    const int r8 = lane & 7;
    const int q4 = lane >> 3;
    const int fRow = (q4 & 1) * 8 + r8;
    const int fCol = (q4 >> 1) * 8;

    const int lrow = tid >> 1;
    const int lcol = (tid & 1) * 64;
    const uint32_t dOff = (uint32_t)(lrow * FLD + lcol) * 2;

    const __half* Qg = g_qkv16 + ((size_t)(b * SEQ + tQ + lrow) * QKVN + h * HDIM + lcol);
    const __half* Kg0 = g_qkv16 + ((size_t)(b * SEQ + lrow) * QKVN + HID + h * HDIM + lcol);
    const __half* Vg0 = g_qkv16 + ((size_t)(b * SEQ + lrow) * QKVN + 2 * HID + h * HDIM + lcol);

#define CP_TILE(dstbase, src)                                   \
    {                                                           \
        uint32_t d = (dstbase) + dOff;                          \
        const __half* sp = (src);                               \
        _Pragma("unroll")                                       \
        for (int i = 0; i < 8; i++) cpasync16(d + i * 16, sp + i * 8); \
        cp_commit();                                            \
    }

    CP_TILE(sQ, Qg);
    CP_TILE(sK, Kg0);
    CP_TILE(sV, Vg0);
    CP_TILE(sK + FTILE, Kg0 + (size_t)128 * QKVN);
    CP_TILE(sV + FTILE, Vg0 + (size_t)128 * QKVN);

    cp_wait4();
    __syncthreads();

    uint32_t qf[8][4];
#pragma unroll
    for (int kk = 0; kk < 8; kk++)
        ldsm4(qf[kk], sQ + (uint32_t)((16 * w + fRow) * FLD + kk * 16 + fCol) * 2);

    float o[16][4];
#pragma unroll
    for (int nt = 0; nt < 16; nt++)
#pragma unroll
        for (int e = 0; e < 4; e++) o[nt][e] = 0.0f;
    float m0 = -INFINITY, m1 = -INFINITY, l0 = 0.0f, l1 = 0.0f;
    const float scale = 0.08838834764831843f;

    for (int j = 0; j < 4; j++) {
        if (j < 3) cp_wait2(); else cp_wait0();
        __syncthreads();
        const uint32_t Kb = sK + (j & 1) * FTILE;
        const uint32_t Vb = sV + (j & 1) * FTILE;

        float s[16][4];
#pragma unroll
        for (int nt = 0; nt < 16; nt++)
#pragma unroll
            for (int e = 0; e < 4; e++) s[nt][e] = 0.0f;
#pragma unroll
        for (int kk = 0; kk < 8; kk++) {
#pragma unroll
            for (int nt2 = 0; nt2 < 8; nt2++) {
                uint32_t t[4];
                ldsm4(t, Kb + (uint32_t)((nt2 * 16 + fRow) * FLD + kk * 16 + fCol) * 2);
                mma16816(s[2 * nt2],     qf[kk], t[0], t[2]);
                mma16816(s[2 * nt2 + 1], qf[kk], t[1], t[3]);
            }
        }
        __syncthreads();
        if (j < 2) CP_TILE(sK + (j & 1) * FTILE, Kg0 + (size_t)(j + 2) * 128 * QKVN);

        float mx0 = -INFINITY, mx1 = -INFINITY;
#pragma unroll
        for (int nt = 0; nt < 16; nt++) {
#pragma unroll
            for (int e = 0; e < 4; e++) s[nt][e] *= scale;
            mx0 = fmaxf(mx0, fmaxf(s[nt][0], s[nt][1]));
            mx1 = fmaxf(mx1, fmaxf(s[nt][2], s[nt][3]));
        }
        mx0 = fmaxf(mx0, __shfl_xor_sync(0xffffffffu, mx0, 1));
        mx0 = fmaxf(mx0, __shfl_xor_sync(0xffffffffu, mx0, 2));
        mx1 = fmaxf(mx1, __shfl_xor_sync(0xffffffffu, mx1, 1));
        mx1 = fmaxf(mx1, __shfl_xor_sync(0xffffffffu, mx1, 2));
        const float mn0 = fmaxf(m0, mx0), mn1 = fmaxf(m1, mx1);
        const float c0 = __expf(m0 - mn0), c1 = __expf(m1 - mn1);
        m0 = mn0; m1 = mn1;
        float rs0 = 0.0f, rs1 = 0.0f;
#pragma unroll
        for (int nt = 0; nt < 16; nt++) {
            s[nt][0] = __expf(s[nt][0] - mn0); s[nt][1] = __expf(s[nt][1] - mn0);
            s[nt][2] = __expf(s[nt][2] - mn1); s[nt][3] = __expf(s[nt][3] - mn1);
            rs0 += s[nt][0] + s[nt][1];
            rs1 += s[nt][2] + s[nt][3];
            o[nt][0] *= c0; o[nt][1] *= c0; o[nt][2] *= c1; o[nt][3] *= c1;
        }
        rs0 += __shfl_xor_sync(0xffffffffu, rs0, 1);
        rs0 += __shfl_xor_sync(0xffffffffu, rs0, 2);
        rs1 += __shfl_xor_sync(0xffffffffu, rs1, 1);
        rs1 += __shfl_xor_sync(0xffffffffu, rs1, 2);
        l0 = l0 * c0 + rs0;
        l1 = l1 * c1 + rs1;

#pragma unroll
        for (int kk = 0; kk < 8; kk++) {
            uint32_t a[4];
            a[0] = packh2(s[2 * kk][0], s[2 * kk][1]);
            a[1] = packh2(s[2 * kk][2], s[2 * kk][3]);
            a[2] = packh2(s[2 * kk + 1][0], s[2 * kk + 1][1]);
            a[3] = packh2(s[2 * kk + 1][2], s[2 * kk + 1][3]);
#pragma unroll
            for (int nt2 = 0; nt2 < 8; nt2++) {
                uint32_t t[4];
                ldsm4t(t, Vb + (uint32_t)((kk * 16 + fRow) * FLD + nt2 * 16 + fCol) * 2);
                mma16816(o[2 * nt2],     a, t[0], t[1]);
                mma16816(o[2 * nt2 + 1], a, t[2], t[3]);
            }
        }
        __syncthreads();
        if (j < 2) CP_TILE(sV + (j & 1) * FTILE, Vg0 + (size_t)(j + 2) * 128 * QKVN);
    }
#undef CP_TILE

    const int gr = lane >> 2;
    const int gc = (lane & 3) * 2;
    const float li0 = 1.0f / l0, li1 = 1.0f / l1;
    const size_t row0 = (size_t)(b * SEQ + tQ + 16 * w + gr) * HID + h * HDIM;
    const size_t row1 = row0 + (size_t)8 * HID;
#pragma unroll
    for (int nt = 0; nt < 16; nt++) {
        const int col = nt * 8 + gc;
        __half2 h0 = __floats2half2_rn(o[nt][0] * li0, o[nt][1] * li0);
        __half2 h1 = __floats2half2_rn(o[nt][2] * li1, o[nt][3] * li1);
        *(__half2*)(g_ctx16 + row0 + col) = h0;
        *(__half2*)(g_ctx16 + row1 + col) = h1;
    }
}

// ---------------- weight transpose + fp32->fp16 convert: W[K,N] -> Wt[N,K] ----
__global__ void __launch_bounds__(256) k_wt(const float* __restrict__ W, __half* __restrict__ Wt,
                                            int K, int N) {
    __shared__ float t[32][33];
    int nb = blockIdx.x * 32, kb = blockIdx.y * 32;
    int tx = threadIdx.x & 31, ty = threadIdx.x >> 5;
#pragma unroll
    for (int j = 0; j < 4; j++)
        t[ty + 8 * j][tx] = W[(size_t)(kb + ty + 8 * j) * N + nb + tx];
    __syncthreads();
#pragma unroll
    for (int j = 0; j < 4; j++)
        Wt[(size_t)(nb + ty + 8 * j) * K + kb + tx] = __float2half(t[tx][ty + 8 * j]);
}

// QKV weights: z selects Wq/Wk/Wv, writes into g_Wqkvt rows z*1024 + n
__global__ void __launch_bounds__(256) k_wt_qkv(const float* __restrict__ Wq,
                                                const float* __restrict__ Wk,
                                                const float* __restrict__ Wv) {
    __shared__ float t[32][33];
    const float* W = (blockIdx.z == 0) ? Wq : (blockIdx.z == 1) ? Wk : Wv;
    int nb = blockIdx.x * 32, kb = blockIdx.y * 32;
    int tx = threadIdx.x & 31, ty = threadIdx.x >> 5;
#pragma unroll
    for (int j = 0; j < 4; j++)
        t[ty + 8 * j][tx] = W[(size_t)(kb + ty + 8 * j) * HID + nb + tx];
    __syncthreads();
    __half* Wt = g_Wqkvt + (size_t)blockIdx.z * HID * HID;
#pragma unroll
    for (int j = 0; j < 4; j++)
        Wt[(size_t)(nb + ty + 8 * j) * HID + kb + tx] = __float2half(t[tx][ty + 8 * j]);
}

// packed qkv bias
__global__ void __launch_bounds__(256) k_bias_pack(const float* __restrict__ qb,
                                                   const float* __restrict__ vb) {
    int i = blockIdx.x * 256 + threadIdx.x;
    float v = 0.0f;
    if (i < HID) v = qb[i];
    else if (i >= 2 * HID) v = vb[i - 2 * HID];
    g_bqkv[i] = v;
}

// ---------------- warp-per-row LayerNorm (no barriers, no smem) ----------------
__device__ __forceinline__ float warpSumF(float v) {
#pragma unroll
    for (int o = 16; o > 0; o >>= 1) v += __shfl_xor_sync(0xffffffffu, v, o);
    return v;
}

// One warp normalizes one row of 1024 floats held in v[8] (float4 each, strided by 32).
// Writes fp32 (if out32) and/or fp16 (if out16).
__device__ __forceinline__ void ln_warp(float4* v, const float* __restrict__ g,
                                        const float* __restrict__ b,
                                        float* __restrict__ out32,
                                        __half* __restrict__ out16, int lane) {
    float s = 0.0f;
#pragma unroll
    for (int i = 0; i < 8; i++) s += v[i].x + v[i].y + v[i].z + v[i].w;
    s = warpSumF(s);
    const float m = s * (1.0f / (float)HID);
    float s2 = 0.0f;
#pragma unroll
    for (int i = 0; i < 8; i++) {
        float dx = v[i].x - m, dy = v[i].y - m, dz = v[i].z - m, dw = v[i].w - m;
        s2 += dx * dx + dy * dy + dz * dz + dw * dw;
    }
    s2 = warpSumF(s2);
    const float r = rsqrtf(s2 * (1.0f / (float)HID) + 1e-7f);
#pragma unroll
    for (int i = 0; i < 8; i++) {
        const int f = i * 32 + lane;
        float4 gv = ((const float4*)g)[f];
        float4 bv = ((const float4*)b)[f];
        float4 o;
        o.x = (v[i].x - m) * r * gv.x + bv.x;
        o.y = (v[i].y - m) * r * gv.y + bv.y;
        o.z = (v[i].z - m) * r * gv.z + bv.z;
        o.w = (v[i].w - m) * r * gv.w + bv.w;
        if (out32) ((float4*)out32)[f] = o;
        if (out16) {
            uint2 u;
            u.x = packh2(o.x, o.y);
            u.y = packh2(o.z, o.w);
            ((uint2*)out16)[f] = u;
        }
    }
}

// embed: (x + pos) -> LN -> g_h (fp32) + g_h16 (fp16). 8 rows per 256-thr CTA.
__global__ void __launch_bounds__(256) k_embed(const float* __restrict__ x,
                                               const float* __restrict__ pos,
                                               const float* __restrict__ g,
                                               const float* __restrict__ b) {
    const int lane = threadIdx.x & 31;
    const int row = blockIdx.x * 8 + (threadIdx.x >> 5);
    const int sPos = row & (SEQ - 1);
    const float4* xr = (const float4*)(x + (size_t)row * HID);
    const float4* pr = (const float4*)(pos + (size_t)sPos * HID);
    float4 v[8];
#pragma unroll
    for (int i = 0; i < 8; i++) {
        float4 a = xr[i * 32 + lane];
        float4 p = pr[i * 32 + lane];
        a.x += p.x; a.y += p.y; a.z += p.z; a.w += p.w;
        v[i] = a;
    }
    ln_warp(v, g, b, g_h + (size_t)row * HID, g_h16 + (size_t)row * HID, lane);
}

// LN1: g_h (pre-LN1, fp32) -> g_attn32 (fp32) + g_attn16 (fp16)
__global__ void __launch_bounds__(256) k_ln1(const float* __restrict__ g,
                                             const float* __restrict__ b) {
    const int lane = threadIdx.x & 31;
    const int row = blockIdx.x * 8 + (threadIdx.x >> 5);
    const float4* xr = (const float4*)(g_h + (size_t)row * HID);
    float4 v[8];
#pragma unroll
    for (int i = 0; i < 8; i++) v[i] = xr[i * 32 + lane];
    ln_warp(v, g, b, g_attn32 + (size_t)row * HID, g_attn16 + (size_t)row * HID, lane);
}

// LN2: g_h (pre-LN2, fp32) -> out (fp32)
__global__ void __launch_bounds__(256) k_ln2(const float* __restrict__ g,
                                             const float* __restrict__ b,
                                             float* __restrict__ out) {
    const int lane = threadIdx.x & 31;
    const int row = blockIdx.x * 8 + (threadIdx.x >> 5);
    const float4* xr = (const float4*)(g_h + (size_t)row * HID);
    float4 v[8];
#pragma unroll
    for (int i = 0; i < 8; i++) v[i] = xr[i * 32 + lane];
    ln_warp(v, g, b, out + (size_t)row * HID, (__half*)nullptr, lane);
}

// ---------------- launch ----------------
extern "C" void kernel_launch(void* const* d_in, const int* in_sizes, int n_in,
                              void* d_out, int out_size) {
    const float* x        = (const float*)d_in[0];
    const float* pos_emb  = (const float*)d_in[1];
    const float* emb_ln_g = (const float*)d_in[2];
    const float* emb_ln_b = (const float*)d_in[3];
    const float* Wq       = (const float*)d_in[4];
    const float* Wk       = (const float*)d_in[5];
    const float* Wv       = (const float*)d_in[6];
    const float* q_bias   = (const float*)d_in[7];
    const float* v_bias   = (const float*)d_in[8];
    const float* Wo       = (const float*)d_in[9];
    const float* bo       = (const float*)d_in[10];
    const float* ln1_g    = (const float*)d_in[11];
    const float* ln1_b    = (const float*)d_in[12];
    const float* Wi       = (const float*)d_in[13];
    const float* bi       = (const float*)d_in[14];
    const float* Wf       = (const float*)d_in[15];
    const float* bf       = (const float*)d_in[16];
    const float* ln2_g    = (const float*)d_in[17];
    const float* ln2_b    = (const float*)d_in[18];
    float* out = (float*)d_out;

    __half *wot, *wit, *wft;
    cudaGetSymbolAddress((void**)&wot, g_Wot);
    cudaGetSymbolAddress((void**)&wit, g_Wit);
    cudaGetSymbolAddress((void**)&wft, g_Wft);

    static cudaStream_t s2 = nullptr;
    static cudaEvent_t evFork = nullptr, evJoin1 = nullptr, evJoin2 = nullptr;
    if (!s2) {
        cudaStreamCreateWithFlags(&s2, cudaStreamNonBlocking);
        cudaEventCreateWithFlags(&evFork, cudaEventDisableTiming);
        cudaEventCreateWithFlags(&evJoin1, cudaEventDisableTiming);
        cudaEventCreateWithFlags(&evJoin2, cudaEventDisableTiming);
    }

    cudaFuncSetAttribute(k_qkv, cudaFuncAttributeMaxDynamicSharedMemorySize, GSM3);
    cudaFuncSetAttribute(k_proj_o, cudaFuncAttributeMaxDynamicSharedMemorySize, GSM3);
    cudaFuncSetAttribute(k_ff1, cudaFuncAttributeMaxDynamicSharedMemorySize, GSM3);
    cudaFuncSetAttribute(k_ff2, cudaFuncAttributeMaxDynamicSharedMemorySize, GSM3);
    cudaFuncSetAttribute(k_flash, cudaFuncAttributeMaxDynamicSharedMemorySize, FSM_TOTAL);

    // fork: weight prep on s2 runs concurrently with embed/qkv/flash on main
    cudaEventRecord(evFork, 0);
    cudaStreamWaitEvent(s2, evFork, 0);
    k_bias_pack<<<QKVN / 256, 256, 0, s2>>>(q_bias, v_bias);
    k_wt_qkv<<<dim3(HID / 32, HID / 32, 3), 256, 0, s2>>>(Wq, Wk, Wv);
    cudaEventRecord(evJoin1, s2);   // qkv weights + bias ready
    k_wt<<<dim3(HID / 32, HID / 32), 256, 0, s2>>>(Wo, wot, HID, HID);
    k_wt<<<dim3(FFDIM / 32, HID / 32), 256, 0, s2>>>(Wi, wit, HID, FFDIM);
    k_wt<<<dim3(HID / 32, FFDIM / 32), 256, 0, s2>>>(Wf, wft, FFDIM, HID);
    cudaEventRecord(evJoin2, s2);   // Wo/Wi/Wf ready

    k_embed<<<MTOT / 8, 256>>>(x, pos_emb, emb_ln_g, emb_ln_b);
    cudaStreamWaitEvent(0, evJoin1, 0);  // need qkv weights now

    dim3 gQKV(QKVN / 128, MTOT / 128);     // (24, 64)
    dim3 gProj(HID / 128, MTOT / 128);     // (8, 64)
    dim3 gFF1(FFDIM / 128, MTOT / 128);    // (24, 64)
    dim3 gFlash(SEQ / 128, NBH);           // (4, 128)

    k_qkv<<<gQKV, 256, GSM3>>>();
    k_flash<<<gFlash, 256, FSM_TOTAL>>>();
    cudaStreamWaitEvent(0, evJoin2, 0);  // need Wo (and later Wi/Wf)
    k_proj_o<<<gProj, 256, GSM3>>>(bo);
    k_ln1<<<MTOT / 8, 256>>>(ln1_g, ln1_b);
    k_ff1<<<gFF1, 256, GSM3>>>(bi);
    k_ff2<<<gProj, 256, GSM3>>>(bf);
    k_ln2<<<MTOT / 8, 256>>>(ln2_g, ln2_b, out);
}